// round 1
// baseline (speedup 1.0000x reference)
#include <cuda_runtime.h>
#include <cuda_bf16.h>
#include <math.h>

// Problem constants
#define Bz      8192
#define NNETS   30
#define NNODES  20
#define NOUT    10
#define DOUT    16
#define INDIM   784
#define NCOL    600          // NNETS*NNODES
#define NPAD    640          // padded to multiple of 64

// Scratch (device globals; zero-initialized .bss — pad columns of W1p stay 0)
__device__ float g_W1p[INDIM * NPAD];     // [k][j] j = n*20+o, cols 600..639 zero
__device__ float g_b1p[NPAD];
__device__ float g_h1[Bz * NPAD];         // relu(x@W1+b1), padded cols garbage/0 (never read)
__device__ float g_u[Bz * NCOL];          // squashed layer-2 output

// ---------------------------------------------------------------------------
// K0: pack W1 into [784, 640] row-major (so GEMM B-operand is contiguous), pad bias
// ---------------------------------------------------------------------------
__global__ void pack_kernel(const float* __restrict__ W1, const float* __restrict__ b1) {
    int idx = blockIdx.x * blockDim.x + threadIdx.x;
    if (idx < INDIM * NCOL) {
        int k = idx / NCOL;
        int j = idx % NCOL;
        int n = j / NNODES;
        int o = j % NNODES;
        g_W1p[k * NPAD + j] = W1[n * (INDIM * NNODES) + k * NNODES + o];
    }
    if (idx < NPAD) {
        g_b1p[idx] = (idx < NCOL) ? b1[idx] : 0.f;
    }
}

// ---------------------------------------------------------------------------
// K1: C[8192,640] = relu(A[8192,784] @ W1p[784,640] + b1p)
// 128x64 tile, BK=16, 256 threads, 8x4 microkernel
// ---------------------------------------------------------------------------
__global__ __launch_bounds__(256) void gemm1_kernel(const float* __restrict__ A) {
    __shared__ float As[16][132];   // padded to reduce store conflicts
    __shared__ float Bs[16][64];

    const int tid = threadIdx.x;
    const int bm  = blockIdx.x & 63;    // 8192/128 = 64 M tiles
    const int bn  = blockIdx.x >> 6;    // 640/64   = 10 N tiles
    const int tx  = tid & 15;
    const int ty  = tid >> 4;

    // A tile loads: 128 rows x 16 cols; each thread 2x float4
    const int arow  = tid >> 2;         // 0..63
    const int acol4 = (tid & 3) * 4;    // 0,4,8,12
    // B tile loads: 16 rows x 64 cols; each thread 1x float4
    const int brow  = tid >> 4;         // 0..15
    const int bcol4 = (tid & 15) * 4;

    const float* Ap = A + (size_t)(bm * 128 + arow) * INDIM + acol4;
    const float* Bp = g_W1p + (size_t)brow * NPAD + bn * 64 + bcol4;

    float acc[8][4];
    #pragma unroll
    for (int i = 0; i < 8; i++)
        #pragma unroll
        for (int j = 0; j < 4; j++) acc[i][j] = 0.f;

    for (int kt = 0; kt < INDIM; kt += 16) {
        float4 a0 = *(const float4*)(Ap + kt);
        float4 a1 = *(const float4*)(Ap + (size_t)64 * INDIM + kt);
        float4 b0 = *(const float4*)(Bp + (size_t)kt * NPAD);

        As[acol4 + 0][arow] = a0.x;
        As[acol4 + 1][arow] = a0.y;
        As[acol4 + 2][arow] = a0.z;
        As[acol4 + 3][arow] = a0.w;
        As[acol4 + 0][arow + 64] = a1.x;
        As[acol4 + 1][arow + 64] = a1.y;
        As[acol4 + 2][arow + 64] = a1.z;
        As[acol4 + 3][arow + 64] = a1.w;
        *(float4*)&Bs[brow][bcol4] = b0;
        __syncthreads();

        #pragma unroll
        for (int k = 0; k < 16; k++) {
            float4 av0 = *(const float4*)&As[k][ty * 8];
            float4 av1 = *(const float4*)&As[k][ty * 8 + 4];
            float4 bv  = *(const float4*)&Bs[k][tx * 4];
            float a[8] = {av0.x, av0.y, av0.z, av0.w, av1.x, av1.y, av1.z, av1.w};
            float b[4] = {bv.x, bv.y, bv.z, bv.w};
            #pragma unroll
            for (int i = 0; i < 8; i++)
                #pragma unroll
                for (int j = 0; j < 4; j++)
                    acc[i][j] = fmaf(a[i], b[j], acc[i][j]);
        }
        __syncthreads();
    }

    // epilogue: bias + relu, vectorized stores
    const int colbase = bn * 64 + tx * 4;
    float4 bias = *(const float4*)&g_b1p[colbase];
    #pragma unroll
    for (int i = 0; i < 8; i++) {
        int row = bm * 128 + ty * 8 + i;
        float4 v;
        v.x = fmaxf(acc[i][0] + bias.x, 0.f);
        v.y = fmaxf(acc[i][1] + bias.y, 0.f);
        v.z = fmaxf(acc[i][2] + bias.z, 0.f);
        v.w = fmaxf(acc[i][3] + bias.w, 0.f);
        *(float4*)&g_h1[(size_t)row * NPAD + colbase] = v;
    }
}

// ---------------------------------------------------------------------------
// K2: per (b, net): h2 = relu(h1 @ W2[n] + b2[n]); u = squash(h2)
// one warp per (b,n); lane e computes h2[e]
// ---------------------------------------------------------------------------
__global__ __launch_bounds__(256) void layer2_kernel(const float* __restrict__ W2,
                                                     const float* __restrict__ b2) {
    int warp = (blockIdx.x * blockDim.x + threadIdx.x) >> 5;
    int lane = threadIdx.x & 31;
    if (warp >= Bz * NNETS) return;
    int b = warp / NNETS;
    int n = warp % NNETS;

    const float* hrow = g_h1 + (size_t)b * NPAD + n * NNODES;
    float hv = (lane < NNODES) ? hrow[lane] : 0.f;

    int e = (lane < NNODES) ? lane : 0;
    const float* w = W2 + n * (NNODES * NNODES) + e;   // stride 20 over d
    float acc = 0.f;
    #pragma unroll
    for (int d = 0; d < NNODES; d++) {
        float hd = __shfl_sync(0xffffffffu, hv, d);
        acc = fmaf(hd, w[d * NNODES], acc);
    }

    float h2 = 0.f;
    if (lane < NNODES) h2 = fmaxf(acc + b2[n * NNODES + lane], 0.f);

    float sq = h2 * h2;
    #pragma unroll
    for (int off = 16; off; off >>= 1) sq += __shfl_xor_sync(0xffffffffu, sq, off);

    float factor = sqrtf(sq) / (1.f + sq);   // squash: t*||t||/(1+||t||^2)
    if (lane < NNODES) g_u[(size_t)b * NCOL + n * NNODES + lane] = h2 * factor;
}

// ---------------------------------------------------------------------------
// K3: priors + 3 routing iterations, fused. One block handles MB=4 batch rows,
// everything resident in shared memory.
// priors[b,o,n,k] = sum_d u[b,n,d] * rw[o,n,d,k]
// ---------------------------------------------------------------------------
#define MB 4
#define SMEM_FLOATS (MB * (NCOL + NOUT*NNETS*DOUT + NOUT*NNETS + NOUT*NNETS + NOUT*DOUT))
#define SMEM_BYTES  (SMEM_FLOATS * 4)

__global__ __launch_bounds__(256) void routing_kernel(const float* __restrict__ rw,
                                                      float* __restrict__ out) {
    extern __shared__ float sm[];
    float* us  = sm;                       // MB*600
    float* pri = us  + MB * NCOL;          // MB*4800  [mb][(o*30+n)*16+k]
    float* lg  = pri + MB * 4800;          // MB*300   [mb][o*30+n]
    float* pb  = lg  + MB * 300;           // MB*300
    float* vv  = pb  + MB * 300;           // MB*160   [mb][o*16+k]

    const int tid = threadIdx.x;
    const int b0  = blockIdx.x * MB;

    for (int idx = tid; idx < MB * NCOL; idx += 256)
        us[idx] = g_u[(size_t)b0 * NCOL + idx];
    for (int idx = tid; idx < MB * 300; idx += 256)
        lg[idx] = 0.f;
    __syncthreads();

    // ---- priors: each thread owns k = tid&15, iterates (o,n) pairs ----
    {
        const int k   = tid & 15;
        const int pr0 = tid >> 4;           // 0..15
        for (int pg = 0; pg < 300; pg += 16) {
            int pair = pg + pr0;            // pair = o*30 + n
            if (pair < 300) {
                int n = pair % NNETS;
                const float* rwp = rw + (size_t)pair * 320 + k;   // (pair*20+d)*16+k
                const float* un  = us + n * NNODES;
                float a0 = 0.f, a1 = 0.f, a2 = 0.f, a3 = 0.f;
                #pragma unroll
                for (int d = 0; d < NNODES; d++) {
                    float w = rwp[d * 16];
                    a0 = fmaf(w, un[d],            a0);
                    a1 = fmaf(w, un[NCOL + d],     a1);
                    a2 = fmaf(w, un[2 * NCOL + d], a2);
                    a3 = fmaf(w, un[3 * NCOL + d], a3);
                }
                pri[            pair * 16 + k] = a0;
                pri[1 * 4800 +  pair * 16 + k] = a1;
                pri[2 * 4800 +  pair * 16 + k] = a2;
                pri[3 * 4800 +  pair * 16 + k] = a3;
            }
        }
    }

    // ---- 3 routing iterations ----
    for (int it = 0; it < 3; it++) {
        __syncthreads();
        // (a) probs = softmax over o (axis=1) of logits, per (mb, n)
        for (int idx = tid; idx < MB * NNETS; idx += 256) {
            int mb = idx / NNETS, n = idx % NNETS;
            const float* L = lg + mb * 300 + n;      // stride 30 over o
            float m = -1e30f;
            #pragma unroll
            for (int o = 0; o < NOUT; o++) m = fmaxf(m, L[o * 30]);
            float e[NOUT];
            float ssum = 0.f;
            #pragma unroll
            for (int o = 0; o < NOUT; o++) { e[o] = expf(L[o * 30] - m); ssum += e[o]; }
            float inv = 1.f / ssum;
            float* P = pb + mb * 300 + n;
            #pragma unroll
            for (int o = 0; o < NOUT; o++) P[o * 30] = e[o] * inv;
        }
        __syncthreads();
        // (b) s[o,k] = sum_n probs[o,n] * priors[o,n,k]
        for (int idx = tid; idx < MB * 160; idx += 256) {
            int mb = idx / 160, r = idx % 160;
            int o = r >> 4, k = r & 15;
            const float* P  = pb  + mb * 300  + o * 30;
            const float* PR = pri + mb * 4800 + o * 480 + k;
            float s = 0.f;
            #pragma unroll
            for (int n = 0; n < NNETS; n++) s = fmaf(P[n], PR[n * 16], s);
            vv[mb * 160 + r] = s;
        }
        __syncthreads();
        // (c) v = squash(s) over k, per (mb, o)
        for (int idx = tid; idx < MB * NOUT; idx += 256) {
            int mb = idx / NOUT, o = idx % NOUT;
            float* V = vv + mb * 160 + o * 16;
            float sq = 0.f;
            #pragma unroll
            for (int k = 0; k < DOUT; k++) sq += V[k] * V[k];
            float f = sqrtf(sq) / (1.f + sq);
            #pragma unroll
            for (int k = 0; k < DOUT; k++) V[k] *= f;
        }
        // (d) logits += sum_k priors * v  (skip on last iteration)
        if (it < 2) {
            __syncthreads();
            for (int idx = tid; idx < MB * 300; idx += 256) {
                int mb = idx / 300, r = idx % 300;    // r = o*30+n
                int o = r / 30;
                const float* PR = pri + mb * 4800 + r * 16;
                const float* V  = vv  + mb * 160  + o * 16;
                float dl = 0.f;
                #pragma unroll
                for (int k = 0; k < DOUT; k++) dl = fmaf(PR[k], V[k], dl);
                lg[mb * 300 + r] += dl;
            }
        }
    }

    __syncthreads();
    for (int idx = tid; idx < MB * 160; idx += 256)
        out[(size_t)b0 * 160 + idx] = vv[idx];
}

// ---------------------------------------------------------------------------
extern "C" void kernel_launch(void* const* d_in, const int* in_sizes, int n_in,
                              void* d_out, int out_size) {
    const float* x  = (const float*)d_in[0];
    const float* W1 = (const float*)d_in[1];
    const float* b1 = (const float*)d_in[2];
    const float* W2 = (const float*)d_in[3];
    const float* b2 = (const float*)d_in[4];
    const float* rw = (const float*)d_in[5];
    float* out = (float*)d_out;

    (void)in_sizes; (void)n_in; (void)out_size;

    pack_kernel<<<(INDIM * NCOL + 255) / 256, 256>>>(W1, b1);
    gemm1_kernel<<<64 * 10, 256>>>(x);
    layer2_kernel<<<(Bz * NNETS) / 8, 256>>>(W2, b2);

    cudaFuncSetAttribute(routing_kernel,
                         cudaFuncAttributeMaxDynamicSharedMemorySize, SMEM_BYTES);
    routing_kernel<<<Bz / MB, 256, SMEM_BYTES>>>(rw, out);
}